// round 14
// baseline (speedup 1.0000x reference)
#include <cuda_runtime.h>

// ARModel p=1, C=1, out_dim=1:
//   out[b,t,n] = (t==0) ? 0 : x[b,t-1,n] * w + bias
// Flat over float4: out4[i] = x4[i - N4]*w + bias unless t(i)==0 (then 0).
//
// R13: persistent single-wave version of the champion. Grid shrinks from
// 9000 blocks (~7.6 waves at 8 CTA/SM) to 1184 = 148 SMs x 8 — one wave.
// Each CTA loops over virtual blocks vb = blockIdx.x + w*1184 (w = 0..7),
// each vb doing exactly the champion's work unit: 4 front-batched .cs
// LDG.128 at stride 2,304,000 float4 (= 4608 rows, 4608 % 288 == 0, so t
// is invariant within a unit). Eliminates (n_waves-1) wave transitions
// (~2360 cyc each) and keeps the LSU pipeline continuously loaded across
// units (loads of w+1 issue while stores of w drain).

#define AR_B 64
#define AR_T 288
#define AR_N 2000
#define AR_N4 (AR_N / 4)                       // 500
#define AR_TOTAL4 (AR_B * AR_T * AR_N4)        // 9,216,000
#define AR_UNROLL 4
#define AR_THREADS 256
#define AR_VBLOCKS (AR_TOTAL4 / (AR_THREADS * AR_UNROLL))  // 9000 virtual blocks
#define AR_STRIDE (AR_VBLOCKS * AR_THREADS)                // 2,304,000 = 4608 rows
#define AR_GRID 1184                                        // 148 SMs x 8 CTA/SM
#define AR_WMAX ((AR_VBLOCKS + AR_GRID - 1) / AR_GRID)      // 8

static_assert(AR_STRIDE % AR_N4 == 0, "stride not row-aligned");
static_assert((AR_STRIDE / AR_N4) % AR_T == 0, "t not invariant across unroll");

__global__ __launch_bounds__(AR_THREADS) void ar_model_kernel(
    const float4* __restrict__ x4,
    const float* __restrict__ w_ptr,
    const float* __restrict__ b_ptr,
    float4* __restrict__ out4)
{
    const float W  = __ldg(w_ptr);
    const float Bi = __ldg(b_ptr);

    #pragma unroll 1
    for (int w = 0; w < AR_WMAX; w++) {
        int vb = blockIdx.x + w * AR_GRID;      // virtual block id
        if (vb >= AR_VBLOCKS) break;

        int base = vb * AR_THREADS + (int)threadIdx.x;

        // t invariant across the 4 strided elements of this unit.
        int row  = base / AR_N4;                // (b*T + t) of element 0
        int t    = row % AR_T;

        if (t != 0) {
            float4 v[AR_UNROLL];
            // Front-batch 4 independent LDG.128 (streaming, evict-first).
            #pragma unroll
            for (int u = 0; u < AR_UNROLL; u++) {
                v[u] = __ldcs(&x4[base + u * AR_STRIDE - AR_N4]);
            }
            #pragma unroll
            for (int u = 0; u < AR_UNROLL; u++) {
                float4 o;
                o.x = fmaf(v[u].x, W, Bi);
                o.y = fmaf(v[u].y, W, Bi);
                o.z = fmaf(v[u].z, W, Bi);
                o.w = fmaf(v[u].w, W, Bi);
                __stcs(&out4[base + u * AR_STRIDE], o);
            }
        } else {
            float4 z;
            z.x = 0.0f; z.y = 0.0f; z.z = 0.0f; z.w = 0.0f;
            #pragma unroll
            for (int u = 0; u < AR_UNROLL; u++) {
                __stcs(&out4[base + u * AR_STRIDE], z);
            }
        }
    }
}

extern "C" void kernel_launch(void* const* d_in, const int* in_sizes, int n_in,
                              void* d_out, int out_size)
{
    const float4* x4 = (const float4*)d_in[0];
    const float*  w  = (const float*)d_in[1];
    const float*  b  = (const float*)d_in[2];
    float4* out4 = (float4*)d_out;

    ar_model_kernel<<<AR_GRID, AR_THREADS>>>(x4, w, b, out4);
}

// round 15
// speedup vs baseline: 1.1224x; 1.1224x over previous
#include <cuda_runtime.h>

// ARModel p=1, C=1, out_dim=1:
//   out[b,t,n] = (t==0) ? 0 : x[b,t-1,n] * w + bias
// Flat over float4: out4[i] = x4[i - N4]*w + bias unless t(i)==0 (then 0).
//
// FINAL champion (R2 geometry + R6 hoist). Full sweep results:
//  - MLP/unroll: 1 -> 43.6us, 4 -> 39.7us (best), 8 -> 40.6us (occ loss)
//  - cache policy: .cs/.cs best; .wb stores and L2::evict_last pinning both
//    worse — DRAM traffic constant ~240MB under every policy (no reuse)
//  - persistent 1-wave grid: worse (per-iteration register reuse serializes
//    loads behind stores; flat grid keeps all loads independent)
//  - index hoist: t invariant across the 4 strided elements because
//    stride = 2,304,000 float4 = 4608 rows and 4608 % 288 == 0
// Achieves ~40.2us kernel = 7.35 TB/s effective (92% of 8 TB/s spec):
// at the practical HBM ceiling for a balanced read+write stream.

#define AR_B 64
#define AR_T 288
#define AR_N 2000
#define AR_N4 (AR_N / 4)                       // 500
#define AR_TOTAL4 (AR_B * AR_T * AR_N4)        // 9,216,000
#define AR_UNROLL 4
#define AR_THREADS 256
#define AR_BLOCKS (AR_TOTAL4 / (AR_THREADS * AR_UNROLL))   // 9000 exact
#define AR_STRIDE (AR_BLOCKS * AR_THREADS)                 // 2,304,000 = 4608 rows

static_assert(AR_STRIDE % AR_N4 == 0, "stride not row-aligned");
static_assert((AR_STRIDE / AR_N4) % AR_T == 0, "t not invariant across unroll");

__global__ __launch_bounds__(AR_THREADS) void ar_model_kernel(
    const float4* __restrict__ x4,
    const float* __restrict__ w_ptr,
    const float* __restrict__ b_ptr,
    float4* __restrict__ out4)
{
    int base = blockIdx.x * AR_THREADS + threadIdx.x;

    // t invariant across the 4 strided elements: compute once per thread.
    int row  = base / AR_N4;          // (b*T + t) of element 0
    int t    = row % AR_T;
    bool live = (t != 0);

    const float W  = __ldg(w_ptr);
    const float Bi = __ldg(b_ptr);

    float4 v[AR_UNROLL];

    if (live) {
        // Front-batch 4 independent LDG.128 (streaming, evict-first).
        #pragma unroll
        for (int u = 0; u < AR_UNROLL; u++) {
            v[u] = __ldcs(&x4[base + u * AR_STRIDE - AR_N4]);
        }
        #pragma unroll
        for (int u = 0; u < AR_UNROLL; u++) {
            float4 o;
            o.x = fmaf(v[u].x, W, Bi);
            o.y = fmaf(v[u].y, W, Bi);
            o.z = fmaf(v[u].z, W, Bi);
            o.w = fmaf(v[u].w, W, Bi);
            __stcs(&out4[base + u * AR_STRIDE], o);
        }
    } else {
        float4 z;
        z.x = 0.0f; z.y = 0.0f; z.z = 0.0f; z.w = 0.0f;
        #pragma unroll
        for (int u = 0; u < AR_UNROLL; u++) {
            __stcs(&out4[base + u * AR_STRIDE], z);
        }
    }
}

extern "C" void kernel_launch(void* const* d_in, const int* in_sizes, int n_in,
                              void* d_out, int out_size)
{
    const float4* x4 = (const float4*)d_in[0];
    const float*  w  = (const float*)d_in[1];
    const float*  b  = (const float*)d_in[2];
    float4* out4 = (float4*)d_out;

    ar_model_kernel<<<AR_BLOCKS, AR_THREADS>>>(x4, w, b, out4);
}

// round 16
// speedup vs baseline: 1.1262x; 1.0034x over previous
#include <cuda_runtime.h>

// ARModel p=1, C=1, out_dim=1:
//   out[b,t,n] = (t==0) ? 0 : x[b,t-1,n] * w + bias
// Flat over float4: out4[i] = x4[i - N4]*w + bias unless t(i)==0 (then 0).
//
// R15: block-size axis (last unswept knob). Identical memory pattern to the
// champion — AR_STRIDE unchanged (4500 blocks x 512 thr = 2,304,000 float4
// = 4608 rows, 4608 % 288 == 0 so t stays invariant across the unroll) —
// only CTA granularity changes: 512 threads, 4 CTAs/SM instead of 8.
// Theory: halved resident-CTA count halves cross-CTA L1tex wavefront-queue
// contention (the residual spread mechanism at MLP_p1=4), with zero change
// to coalescing, cache policy (.cs both streams), or MLP.
// Sweep record: unroll {1,4,8} -> 4 best; policy {.cs/.cs,.cs/.wb,pin} ->
// .cs/.cs best; flat vs persistent -> flat best; threads {256, 512} <- now.

#define AR_B 64
#define AR_T 288
#define AR_N 2000
#define AR_N4 (AR_N / 4)                       // 500
#define AR_TOTAL4 (AR_B * AR_T * AR_N4)        // 9,216,000
#define AR_UNROLL 4
#define AR_THREADS 512
#define AR_BLOCKS (AR_TOTAL4 / (AR_THREADS * AR_UNROLL))   // 4500 exact
#define AR_STRIDE (AR_BLOCKS * AR_THREADS)                 // 2,304,000 = 4608 rows

static_assert(AR_STRIDE % AR_N4 == 0, "stride not row-aligned");
static_assert((AR_STRIDE / AR_N4) % AR_T == 0, "t not invariant across unroll");

__global__ __launch_bounds__(AR_THREADS) void ar_model_kernel(
    const float4* __restrict__ x4,
    const float* __restrict__ w_ptr,
    const float* __restrict__ b_ptr,
    float4* __restrict__ out4)
{
    int base = blockIdx.x * AR_THREADS + threadIdx.x;

    // t invariant across the 4 strided elements: compute once per thread.
    int row  = base / AR_N4;          // (b*T + t) of element 0
    int t    = row % AR_T;
    bool live = (t != 0);

    const float W  = __ldg(w_ptr);
    const float Bi = __ldg(b_ptr);

    float4 v[AR_UNROLL];

    if (live) {
        // Front-batch 4 independent LDG.128 (streaming, evict-first).
        #pragma unroll
        for (int u = 0; u < AR_UNROLL; u++) {
            v[u] = __ldcs(&x4[base + u * AR_STRIDE - AR_N4]);
        }
        #pragma unroll
        for (int u = 0; u < AR_UNROLL; u++) {
            float4 o;
            o.x = fmaf(v[u].x, W, Bi);
            o.y = fmaf(v[u].y, W, Bi);
            o.z = fmaf(v[u].z, W, Bi);
            o.w = fmaf(v[u].w, W, Bi);
            __stcs(&out4[base + u * AR_STRIDE], o);
        }
    } else {
        float4 z;
        z.x = 0.0f; z.y = 0.0f; z.z = 0.0f; z.w = 0.0f;
        #pragma unroll
        for (int u = 0; u < AR_UNROLL; u++) {
            __stcs(&out4[base + u * AR_STRIDE], z);
        }
    }
}

extern "C" void kernel_launch(void* const* d_in, const int* in_sizes, int n_in,
                              void* d_out, int out_size)
{
    const float4* x4 = (const float4*)d_in[0];
    const float*  w  = (const float*)d_in[1];
    const float*  b  = (const float*)d_in[2];
    float4* out4 = (float4*)d_out;

    ar_model_kernel<<<AR_BLOCKS, AR_THREADS>>>(x4, w, b, out4);
}